// round 5
// baseline (speedup 1.0000x reference)
#include <cuda_runtime.h>

// Problem constants (fixed by the dataset shapes)
#define HWC   65536      // 256*256
#define BATCH 64
#define NATT  4096
#define MREP  2048

#define NPIX        (BATCH * HWC)          // 4,194,304 pixels
#define PACK_BLOCKS (NPIX / 256)           // 16384
#define GR_BLOCKS   ((BATCH * MREP) / 256) // 512: thread t = repel item t + attract pair t

// 64 MiB packed scratch: {h, off_y, off_x, pad} per pixel. One 16B gather per
// corner instead of three scattered 4B gathers -> 3x fewer L1tex wavefronts.
__device__ float4 g_pack[NPIX];

// Accumulators: [0]=S_attract, [1]=N_attract, [2]=S_repel, [3]=N_repel.
// Zero-initialized at load; finalizing block re-zeros for graph-replay determinism.
__device__ double g_acc[4];
__device__ unsigned int g_done;

// ---------------------------------------------------------------------------
// Pass 1: coalesced pack of (h, off_y, off_x) planes into float4 per pixel.
// ---------------------------------------------------------------------------
__global__ __launch_bounds__(256)
void pack_kernel(const float* __restrict__ oh, const float* __restrict__ ooff) {
    int p = blockIdx.x * 256 + threadIdx.x;     // [0, NPIX)
    int b = p >> 16;
    int i = p & (HWC - 1);
    const float* base = ooff + (size_t)b * 2 * HWC;
    float h  = __ldg(oh + p);
    float oy = __ldg(base + i);
    float ox = __ldg(base + i + HWC);
    g_pack[p] = make_float4(h, oy, ox, 0.0f);
}

// ---------------------------------------------------------------------------
// Pass 2: gathers + IoU + global reduction.
// ---------------------------------------------------------------------------
__device__ __forceinline__ float iou_f(float hA, float yA, float xA,
                                       float hB, float yB, float xB) {
    float areaA = hA * hA * 0.41f;
    float areaB = hB * hB * 0.41f;
    float y_min_max = fmaxf(yA - hA * 0.5f,         yB - hB * 0.5f);
    float x_min_max = fmaxf(xA - 0.41f * hA * 0.5f, xB - 0.41f * hB * 0.5f);
    float y_max_min = fminf(yA + hA * 0.5f,         yB + hB * 0.5f);
    float x_max_min = fminf(xA + 0.41f * hA * 0.5f, xB + 0.41f * hB * 0.5f);
    float I = fmaxf(y_max_min - y_min_max, 0.0f) * fmaxf(x_max_min - x_min_max, 0.0f);
    float U = areaA + areaB - I;
    return I / (U + 1e-6f);
}

// Block-wide reduction of 4 partials -> 4 double atomics. blockDim.x == 256.
__device__ __forceinline__ void block_reduce4(float v0, float v1, float v2, float v3) {
    #pragma unroll
    for (int o = 16; o > 0; o >>= 1) {
        v0 += __shfl_down_sync(0xFFFFFFFFu, v0, o);
        v1 += __shfl_down_sync(0xFFFFFFFFu, v1, o);
        v2 += __shfl_down_sync(0xFFFFFFFFu, v2, o);
        v3 += __shfl_down_sync(0xFFFFFFFFu, v3, o);
    }
    __shared__ float s[4][8];
    int lane = threadIdx.x & 31;
    int warp = threadIdx.x >> 5;
    if (lane == 0) { s[0][warp] = v0; s[1][warp] = v1; s[2][warp] = v2; s[3][warp] = v3; }
    __syncthreads();
    if (warp == 0) {
        v0 = (lane < 8) ? s[0][lane] : 0.0f;
        v1 = (lane < 8) ? s[1][lane] : 0.0f;
        v2 = (lane < 8) ? s[2][lane] : 0.0f;
        v3 = (lane < 8) ? s[3][lane] : 0.0f;
        #pragma unroll
        for (int o = 4; o > 0; o >>= 1) {
            v0 += __shfl_down_sync(0x000000FFu, v0, o);
            v1 += __shfl_down_sync(0x000000FFu, v1, o);
            v2 += __shfl_down_sync(0x000000FFu, v2, o);
            v3 += __shfl_down_sync(0x000000FFu, v3, o);
        }
        if (lane == 0) {
            if (v0 != 0.0f) atomicAdd(&g_acc[0], (double)v0);
            atomicAdd(&g_acc[1], (double)v1);
            if (v2 != 0.0f) atomicAdd(&g_acc[2], (double)v2);
            atomicAdd(&g_acc[3], (double)v3);
        }
    }
}

__global__ __launch_bounds__(256)
void gather_kernel(const float* __restrict__ pre_off,
                   const int*   __restrict__ attract,
                   const int*   __restrict__ repel,
                   const unsigned char* __restrict__ mask_att,
                   const unsigned char* __restrict__ mask_rep,
                   float* __restrict__ out) {
    int t = blockIdx.x * 256 + threadIdx.x;   // [0, 131072)

    // ---------------- repel item t: 8 float4 gathers ----------------
    float rep_s = 0.f, rep_n = 0.f;
    {
        int b = t >> 11;                      // / MREP
        const float4* pk = g_pack + ((size_t)b << 16);

        const int4* rp = reinterpret_cast<const int4*>(repel) + (size_t)t * 2;
        int4 i0 = rp[0];
        int4 i1 = rp[1];
        int ind[8] = {i0.x, i0.y, i0.z, i0.w, i1.x, i1.y, i1.z, i1.w};

        float4 c[8];
        #pragma unroll
        for (int k = 0; k < 8; k++) c[k] = __ldg(pk + ind[k]);

        float hm[2], y[2], x[2];
        #pragma unroll
        for (int j = 0; j < 2; j++) {
            float hs = 0.f, sy = 0.f, sx = 0.f;
            #pragma unroll
            for (int k = 0; k < 4; k++) {
                hs += c[j * 4 + k].x;
                sy += c[j * 4 + k].y;
                sx += c[j * 4 + k].z;
            }
            hm[j] = hs * 0.25f;
            // mean of (off + OFFSETS): OFFSETS contributes +0.5 per channel
            y[j] = sy * 0.25f + 0.5f;
            x[j] = sx * 0.25f + 0.5f;
        }
        float2 po = reinterpret_cast<const float2*>(pre_off)[t];
        y[1] += po.x;
        x[1] += po.y;

        float v = iou_f(expf(hm[0]), y[0], x[0], expf(hm[1]), y[1], x[1]);
        if (mask_rep[t]) { rep_s = v; rep_n = 1.0f; }
    }

    // ---------------- attract pair t: items 2t, 2t+1 (8 gathers) ----------------
    float att_s = 0.f, att_n = 0.f;
    {
        int gid0 = 2 * t;
        int b = gid0 >> 12;                   // / NATT (pair shares batch)
        const float4* pk = g_pack + ((size_t)b << 16);

        const int4* ap = reinterpret_cast<const int4*>(attract) + gid0;
        int4 qa = ap[0];
        int4 qb = ap[1];
        uint2 m2 = reinterpret_cast<const uint2*>(mask_att)[t];
        unsigned int mm[2] = {m2.x, m2.y};

        int ind[8] = {qa.x, qa.y, qa.z, qa.w, qb.x, qb.y, qb.z, qb.w};
        float4 c[8];
        #pragma unroll
        for (int k = 0; k < 8; k++) c[k] = __ldg(pk + ind[k]);

        // OFFSETS = [[0,0],[1,0],[0,1],[1,1]]: channel0 += {0,1,0,1}, channel1 += {0,0,1,1}
        const float kx[4] = {0.f, 1.f, 0.f, 1.f};
        const float ky[4] = {0.f, 0.f, 1.f, 1.f};

        #pragma unroll
        for (int it = 0; it < 2; it++) {
            int base = it * 4;
            float hmv = 0.f, o0m = 0.f, o1m = 0.f;
            float co0[4], co1[4];
            #pragma unroll
            for (int k = 0; k < 4; k++) {
                co0[k] = c[base + k].y + kx[k];
                co1[k] = c[base + k].z + ky[k];
                hmv += c[base + k].x;
                o0m += co0[k];
                o1m += co1[k];
            }
            hmv *= 0.25f; o0m *= 0.25f; o1m *= 0.25f;
            float hB = expf(hmv);

            unsigned int m = mm[it];
            #pragma unroll
            for (int k = 0; k < 4; k++) {
                if ((m >> (8 * k)) & 0xFFu) {
                    att_s += 1.0f - iou_f(expf(c[base + k].x), co0[k], co1[k],
                                          hB, o0m, o1m);
                    att_n += 1.0f;
                }
            }
        }
    }

    block_reduce4(att_s, att_n, rep_s, rep_n);

    // ---------------- last-block finalize + reset ----------------
    __threadfence();
    __shared__ bool s_last;
    if (threadIdx.x == 0) {
        unsigned int ticket = atomicAdd(&g_done, 1u);
        s_last = (ticket == (unsigned int)(GR_BLOCKS - 1));
    }
    __syncthreads();
    if (s_last && threadIdx.x == 0) {
        double sa = g_acc[0], na = g_acc[1];
        double sr = g_acc[2], nr = g_acc[3];
        out[0] = (float)(sa / (na + 1e-4) + sr / (nr + 1e-4));
        g_acc[0] = 0.0; g_acc[1] = 0.0; g_acc[2] = 0.0; g_acc[3] = 0.0;
        __threadfence();
        g_done = 0u;
    }
}

extern "C" void kernel_launch(void* const* d_in, const int* in_sizes, int n_in,
                              void* d_out, int out_size) {
    const float* output_h    = (const float*)d_in[0];  // [64,1,256,256]
    const float* output_off  = (const float*)d_in[1];  // [64,2,256,256]
    // d_in[2], d_in[3]: target_h / target_off — unused by the reference
    const float* pre_off     = (const float*)d_in[4];  // [64,2048,2]
    const int*   attract     = (const int*)  d_in[5];  // [64,4096,4]
    const int*   repel       = (const int*)  d_in[6];  // [64,2048,2,4]
    const unsigned char* mask_attract = (const unsigned char*)d_in[7];  // [64,4096,4] bool
    const unsigned char* mask_repel   = (const unsigned char*)d_in[8];  // [64,2048,1] bool
    float* out = (float*)d_out;

    pack_kernel<<<PACK_BLOCKS, 256>>>(output_h, output_off);
    gather_kernel<<<GR_BLOCKS, 256>>>(pre_off, attract, repel,
                                      mask_attract, mask_repel, out);
}